// round 4
// baseline (speedup 1.0000x reference)
#include <cuda_runtime.h>
#include <cuda_bf16.h>
#include <stdint.h>

#define N_NODES 16384
#define FDIM    128
#define NCLS    40

#define BM 64
#define BK 32
#define KTILES (N_NODES / BK)   // 512
#define STAGES 4

// Scratch (static device globals — no allocation allowed)
__device__ float         g_support[(size_t)N_NODES * FDIM];   // 8 MB
__device__ __nv_bfloat16 g_featb [(size_t)N_NODES * FDIM];    // 4 MB

__device__ __forceinline__ uint32_t smaddr(const void* p) {
    return (uint32_t)__cvta_generic_to_shared(p);
}

// ---------------------------------------------------------------------------
// Convert x (fp32) -> g_featb (bf16)
// ---------------------------------------------------------------------------
__global__ void cvt_x_kernel(const float* __restrict__ in) {
    int i = blockIdx.x * blockDim.x + threadIdx.x;
    int stride = gridDim.x * blockDim.x;
    const int n4 = N_NODES * FDIM / 4;
    const float4* in4 = (const float4*)in;
    __nv_bfloat162* ob = (__nv_bfloat162*)g_featb;
    for (; i < n4; i += stride) {
        float4 v = in4[i];
        ob[2 * i]     = __float22bfloat162_rn(make_float2(v.x, v.y));
        ob[2 * i + 1] = __float22bfloat162_rn(make_float2(v.z, v.w));
    }
}

// ---------------------------------------------------------------------------
// SpMM: g_support[N,128] = adj(fp32) @ g_featb[N,128]
// CTA tile 64(M) x 128(N), BK=32, 256 threads, occ 2, 4-stage cp.async.
// A: cp.async fp32 (swizzled 8KB/stage); converted to bf16 in registers at
//    fragment-load time (ld.shared.v2.f32 + cvt.rn.bf16x2) — no ldmatrix, no
//    LDG scoreboard dependency anywhere.
// B: cp.async bf16 (swizzled 8KB/stage) + ldmatrix.trans.
// mma.sync.m16n8k16 bf16/f32. Warp grid 2(M) x 4(N), 32x32 per warp.
// ---------------------------------------------------------------------------
__global__ void __launch_bounds__(256, 2)
spmm_kernel(const float* __restrict__ A) {
    extern __shared__ char smem[];
    char* As = smem;                        // STAGES * 64*32*4B  = 4*8192
    char* Bs = smem + STAGES * 8192;        // STAGES * 32*128*2B = 4*8192
    const uint32_t as0 = smaddr(As);
    const uint32_t bs0 = smaddr(Bs);

    const int t    = threadIdx.x;
    const int lane = t & 31;
    const int warp = t >> 5;
    const int wm = warp & 1;       // 0..1 (M groups of 32)
    const int wn = warp >> 1;      // 0..3 (N groups of 32)
    const int m0 = blockIdx.x * BM;

    float acc[2][4][4];
    #pragma unroll
    for (int i = 0; i < 2; ++i)
        #pragma unroll
        for (int j = 0; j < 4; ++j)
            #pragma unroll
            for (int k = 0; k < 4; ++k) acc[i][j][k] = 0.f;

    const float* Abase = A + (size_t)m0 * N_NODES;

    // A tile: 64 rows x 32 floats (128B/row = 8 chunks of 16B), swizzled c^(r&7)
    auto cpA = [&](int kt, int slot) {
        const uint32_t sbase = as0 + slot * 8192;
        #pragma unroll
        for (int p = 0; p < 2; ++p) {
            int idx = t + p * 256;           // 0..511
            int r = idx >> 3;                // 0..63
            int c = idx & 7;                 // 16B chunk
            uint32_t soff = r * 128 + ((c ^ (r & 7)) << 4);
            const float* g = Abase + (size_t)r * N_NODES + kt * BK + c * 4;
            asm volatile("cp.async.cg.shared.global [%0], [%1], 16;\n"
                         :: "r"(sbase + soff), "l"(g));
        }
    };
    // B tile: 32 rows(k) x 128 bf16 (256B/row = 16 chunks), swizzled c^((r&7)<<1)
    auto cpB = [&](int kt, int slot) {
        const char* gsrc = (const char*)(g_featb + (size_t)kt * BK * FDIM);
        const uint32_t sbase = bs0 + slot * 8192;
        #pragma unroll
        for (int p = 0; p < 2; ++p) {
            int idx = t + p * 256;           // 0..511
            int r = idx >> 4;                // 0..31
            int c = idx & 15;
            uint32_t soff = r * 256 + ((c ^ ((r & 7) << 1)) << 4);
            asm volatile("cp.async.cg.shared.global [%0], [%1], 16;\n"
                         :: "r"(sbase + soff), "l"(gsrc + (size_t)r * 256 + c * 16));
        }
    };

    auto compute = [&](int slot) {
        const uint32_t ab = as0 + slot * 8192;
        const uint32_t bb = bs0 + slot * 8192;
        #pragma unroll
        for (int ks = 0; ks < 2; ++ks) {      // two k16 steps per BK=32
            uint32_t a[2][4];
            #pragma unroll
            for (int mt = 0; mt < 2; ++mt) {
                const int R0 = wm * 32 + mt * 16 + (lane >> 2);
                const int K0 = ks * 16 + (lane & 3) * 2;
                #pragma unroll
                for (int j = 0; j < 4; ++j) {
                    const int R = R0 + ((j & 1) << 3);       // +8 for odd j
                    const int K = K0 + ((j >> 1) << 3);      // +8 for j>=2
                    uint32_t addr = ab + R * 128 + (((K >> 2) ^ (R & 7)) << 4) + ((K & 3) << 2);
                    float f0, f1;
                    asm volatile("ld.shared.v2.f32 {%0,%1}, [%2];\n"
                                 : "=f"(f0), "=f"(f1) : "r"(addr));
                    __nv_bfloat162 h = __float22bfloat162_rn(make_float2(f0, f1));
                    a[mt][j] = *(uint32_t*)&h;
                }
            }
            uint32_t b[4][2];
            #pragma unroll
            for (int nt = 0; nt < 4; ++nt) {
                int r = ks * 16 + (lane & 15);
                int c = wn * 4 + nt;
                uint32_t addr = bb + r * 256 + ((c ^ ((r & 7) << 1)) << 4);
                asm volatile("ldmatrix.sync.aligned.m8n8.x2.trans.shared.b16 {%0,%1}, [%2];\n"
                    : "=r"(b[nt][0]), "=r"(b[nt][1]) : "r"(addr));
            }
            #pragma unroll
            for (int mt = 0; mt < 2; ++mt)
                #pragma unroll
                for (int nt = 0; nt < 4; ++nt) {
                    asm volatile(
                        "mma.sync.aligned.m16n8k16.row.col.f32.bf16.bf16.f32 "
                        "{%0,%1,%2,%3}, {%4,%5,%6,%7}, {%8,%9}, {%0,%1,%2,%3};\n"
                        : "+f"(acc[mt][nt][0]), "+f"(acc[mt][nt][1]),
                          "+f"(acc[mt][nt][2]), "+f"(acc[mt][nt][3])
                        : "r"(a[mt][0]), "r"(a[mt][1]), "r"(a[mt][2]), "r"(a[mt][3]),
                          "r"(b[nt][0]), "r"(b[nt][1]));
                }
        }
    };

    // Prologue: fill STAGES-1 = 3 stages
    #pragma unroll
    for (int s = 0; s < STAGES - 1; ++s) {
        cpA(s, s);
        cpB(s, s);
        asm volatile("cp.async.commit_group;\n");
    }

    for (int it = 0; it < KTILES; ++it) {
        const int ahead = KTILES - it;       // tiles remaining incl. `it`
        if (ahead >= 3)      asm volatile("cp.async.wait_group 2;\n");
        else if (ahead == 2) asm volatile("cp.async.wait_group 1;\n");
        else                 asm volatile("cp.async.wait_group 0;\n");
        __syncthreads();
        if (it + STAGES - 1 < KTILES) {
            const int slot = (it + STAGES - 1) % STAGES;   // == (it-1)%STAGES, freed
            cpA(it + STAGES - 1, slot);
            cpB(it + STAGES - 1, slot);
            asm volatile("cp.async.commit_group;\n");
        }
        compute(it % STAGES);
    }

    // Epilogue: fragment -> g_support (fp32, row-major)
    float* Cp = g_support + (size_t)m0 * FDIM;
    #pragma unroll
    for (int mt = 0; mt < 2; ++mt) {
        int r0 = wm * 32 + mt * 16 + (lane >> 2);
        #pragma unroll
        for (int nt = 0; nt < 4; ++nt) {
            int c0 = wn * 32 + nt * 8 + (lane & 3) * 2;
            *(float2*)(Cp + (size_t)r0 * FDIM + c0)       = make_float2(acc[mt][nt][0], acc[mt][nt][1]);
            *(float2*)(Cp + (size_t)(r0 + 8) * FDIM + c0) = make_float2(acc[mt][nt][2], acc[mt][nt][3]);
        }
    }
}

// ---------------------------------------------------------------------------
// h = relu( [X | g_support] @ W + b ), W is [256,128].
// Writes fp32 to `out`; optionally also bf16 to g_featb (input to next SpMM).
// ---------------------------------------------------------------------------
__global__ void __launch_bounds__(256)
sage_linear_kernel(const float* __restrict__ X,
                   const float* __restrict__ W,
                   const float* __restrict__ bias,
                   float* __restrict__ out,
                   int write_bf16) {
    __shared__ float INs[64][16];
    __shared__ float Ws[16][128];
    const int t  = threadIdx.x;
    const int tr = t >> 5;
    const int tc = t & 31;
    const int row0 = blockIdx.x * 64;

    float acc[8][4];
    #pragma unroll
    for (int i = 0; i < 8; ++i)
        #pragma unroll
        for (int j = 0; j < 4; ++j) acc[i][j] = 0.f;

    for (int kb = 0; kb < 16; ++kb) {
        const int kbase = kb * 16;
        #pragma unroll
        for (int j = 0; j < 4; ++j) {
            int idx = t + j * 256;
            int r = idx >> 4, kk = idx & 15;
            int k = kbase + kk;
            float v;
            if (k < FDIM) v = X[(size_t)(row0 + r) * FDIM + k];
            else          v = g_support[(size_t)(row0 + r) * FDIM + (k - FDIM)];
            INs[r][kk] = v;
        }
        #pragma unroll
        for (int j = 0; j < 8; ++j) {
            int idx = t + j * 256;
            int wr = idx >> 7, wc = idx & 127;
            Ws[wr][wc] = W[(size_t)(kbase + wr) * FDIM + wc];
        }
        __syncthreads();
        #pragma unroll
        for (int kk = 0; kk < 16; ++kk) {
            float4 w = *(const float4*)&Ws[kk][tc * 4];
            #pragma unroll
            for (int i = 0; i < 8; ++i) {
                float xv = INs[tr * 8 + i][kk];
                acc[i][0] = fmaf(xv, w.x, acc[i][0]);
                acc[i][1] = fmaf(xv, w.y, acc[i][1]);
                acc[i][2] = fmaf(xv, w.z, acc[i][2]);
                acc[i][3] = fmaf(xv, w.w, acc[i][3]);
            }
        }
        __syncthreads();
    }

    const float4 bv = *(const float4*)&bias[tc * 4];
    #pragma unroll
    for (int i = 0; i < 8; ++i) {
        int r = row0 + tr * 8 + i;
        float4 o;
        o.x = fmaxf(acc[i][0] + bv.x, 0.f);
        o.y = fmaxf(acc[i][1] + bv.y, 0.f);
        o.z = fmaxf(acc[i][2] + bv.z, 0.f);
        o.w = fmaxf(acc[i][3] + bv.w, 0.f);
        *(float4*)&out[(size_t)r * FDIM + tc * 4] = o;
        if (write_bf16) {
            __nv_bfloat162 lo = __float22bfloat162_rn(make_float2(o.x, o.y));
            __nv_bfloat162 hi = __float22bfloat162_rn(make_float2(o.z, o.w));
            uint2 v;
            v.x = *(uint32_t*)&lo;
            v.y = *(uint32_t*)&hi;
            *(uint2*)&g_featb[(size_t)r * FDIM + tc * 4] = v;
        }
    }
}

// ---------------------------------------------------------------------------
// logits = h2 @ Wl + bl ; log_probs = logits - logsumexp(logits)
// ---------------------------------------------------------------------------
__global__ void __launch_bounds__(128)
classifier_kernel(const float* __restrict__ H,
                  const float* __restrict__ Wl,
                  const float* __restrict__ bl,
                  float* __restrict__ logp,
                  float* __restrict__ logits) {
    extern __shared__ float sh[];
    float* Hs  = sh;                  // 128*129
    float* Wls = sh + 128 * 129;      // 128*40
    float* bls = Wls + 128 * NCLS;    // 40
    const int t = threadIdx.x;
    const int row0 = blockIdx.x * 128;

    for (int j = 0; j < 128; ++j)
        Hs[j * 129 + t] = H[(size_t)(row0 + j) * FDIM + t];
    for (int idx = t; idx < 128 * NCLS; idx += 128)
        Wls[idx] = Wl[idx];
    if (t < NCLS) bls[t] = bl[t];
    __syncthreads();

    float acc[NCLS];
    #pragma unroll
    for (int c = 0; c < NCLS; ++c) acc[c] = bls[c];

    const float* hr = &Hs[t * 129];
    #pragma unroll 4
    for (int k = 0; k < FDIM; ++k) {
        float xv = hr[k];
        #pragma unroll
        for (int c = 0; c < NCLS; c += 4) {
            float4 w = *(const float4*)&Wls[k * NCLS + c];
            acc[c + 0] = fmaf(xv, w.x, acc[c + 0]);
            acc[c + 1] = fmaf(xv, w.y, acc[c + 1]);
            acc[c + 2] = fmaf(xv, w.z, acc[c + 2]);
            acc[c + 3] = fmaf(xv, w.w, acc[c + 3]);
        }
    }

    float m = acc[0];
    #pragma unroll
    for (int c = 1; c < NCLS; ++c) m = fmaxf(m, acc[c]);
    float s = 0.f;
    #pragma unroll
    for (int c = 0; c < NCLS; ++c) s += __expf(acc[c] - m);
    float lse = m + __logf(s);

    size_t ro = (size_t)(row0 + t) * NCLS;
    #pragma unroll
    for (int c = 0; c < NCLS; ++c) {
        logits[ro + c] = acc[c];
        logp[ro + c]   = acc[c] - lse;
    }
}

// ---------------------------------------------------------------------------
extern "C" void kernel_launch(void* const* d_in, const int* in_sizes, int n_in,
                              void* d_out, int out_size) {
    (void)in_sizes; (void)n_in; (void)out_size;
    const float* x   = (const float*)d_in[0];
    const float* adj = (const float*)d_in[1];
    const float* W1  = (const float*)d_in[2];
    const float* b1  = (const float*)d_in[3];
    const float* W2  = (const float*)d_in[4];
    const float* b2  = (const float*)d_in[5];
    const float* Wl  = (const float*)d_in[6];
    const float* bl  = (const float*)d_in[7];

    float* out    = (float*)d_out;
    float* logp   = out;                                  // [N, 40]
    float* h1     = logp + (size_t)N_NODES * NCLS;        // [N, 128]
    float* h2     = h1 + (size_t)N_NODES * FDIM;          // [N, 128]
    float* logits = h2 + (size_t)N_NODES * FDIM;          // [N, 40]

    const int cls_smem  = (128 * 129 + 128 * NCLS + NCLS) * (int)sizeof(float);
    const int spmm_smem = STAGES * 8192 * 2;   // 64 KB
    cudaFuncSetAttribute(spmm_kernel, cudaFuncAttributeMaxDynamicSharedMemorySize, spmm_smem);
    cudaFuncSetAttribute(classifier_kernel, cudaFuncAttributeMaxDynamicSharedMemorySize, cls_smem);

    // 1) x -> bf16
    cvt_x_kernel<<<512, 256>>>(x);
    // 2) support = adj @ x
    spmm_kernel<<<N_NODES / BM, 256, spmm_smem>>>(adj);
    // 3) h1 = relu([x|s]@W1 + b1)  (also emits bf16 h1 into g_featb)
    sage_linear_kernel<<<N_NODES / 64, 256>>>(x, W1, b1, h1, 1);
    // 4) support = adj @ h1
    spmm_kernel<<<N_NODES / BM, 256, spmm_smem>>>(adj);
    // 5) h2 = relu([h1|s]@W2 + b2)
    sage_linear_kernel<<<N_NODES / 64, 256>>>(h1, W2, b2, h2, 0);
    // 6) logits + log_softmax
    classifier_kernel<<<N_NODES / 128, 128, cls_smem>>>(h2, Wl, bl, logp, logits);
}

// round 5
// speedup vs baseline: 1.8009x; 1.8009x over previous
#include <cuda_runtime.h>
#include <cuda_bf16.h>
#include <stdint.h>

#define N_NODES 16384
#define FDIM    128
#define NCLS    40

#define BM 64
#define BK 64
#define KTILES (N_NODES / BK)   // 256
#define STAGES 4

// Scratch (static device globals — no allocation allowed)
__device__ float         g_support[(size_t)N_NODES * FDIM];   // 8 MB
__device__ __nv_bfloat16 g_featb [(size_t)N_NODES * FDIM];    // 4 MB

__device__ __forceinline__ uint32_t smaddr(const void* p) {
    return (uint32_t)__cvta_generic_to_shared(p);
}

__device__ __forceinline__ void mbar_init(uint32_t a, uint32_t cnt) {
    asm volatile("mbarrier.init.shared.b64 [%0], %1;" :: "r"(a), "r"(cnt) : "memory");
}
__device__ __forceinline__ void mbar_arrive(uint32_t a) {
    asm volatile("mbarrier.arrive.release.cta.shared.b64 _, [%0];" :: "r"(a) : "memory");
}
// Blocks while the barrier's phase == parity.
__device__ __forceinline__ void mbar_wait(uint32_t a, uint32_t parity) {
    uint32_t done;
    asm volatile(
        "{\n\t.reg .pred p;\n\t"
        "mbarrier.try_wait.parity.acquire.cta.shared::cta.b64 p, [%1], %2;\n\t"
        "selp.b32 %0, 1, 0, p;\n\t}"
        : "=r"(done) : "r"(a), "r"(parity) : "memory");
    if (!done) {
        asm volatile(
            "{\n\t.reg .pred P1;\n\t"
            "WAIT_LOOP_%=:\n\t"
            "mbarrier.try_wait.parity.acquire.cta.shared::cta.b64 P1, [%0], %1, 0x989680;\n\t"
            "@P1 bra.uni WAIT_DONE_%=;\n\t"
            "bra.uni WAIT_LOOP_%=;\n\t"
            "WAIT_DONE_%=:\n\t}"
            :: "r"(a), "r"(parity) : "memory");
    }
}

// ---------------------------------------------------------------------------
// Convert x (fp32) -> g_featb (bf16)
// ---------------------------------------------------------------------------
__global__ void cvt_x_kernel(const float* __restrict__ in) {
    int i = blockIdx.x * blockDim.x + threadIdx.x;
    int stride = gridDim.x * blockDim.x;
    const int n4 = N_NODES * FDIM / 4;
    const float4* in4 = (const float4*)in;
    __nv_bfloat162* ob = (__nv_bfloat162*)g_featb;
    for (; i < n4; i += stride) {
        float4 v = in4[i];
        ob[2 * i]     = __float22bfloat162_rn(make_float2(v.x, v.y));
        ob[2 * i + 1] = __float22bfloat162_rn(make_float2(v.z, v.w));
    }
}

// ---------------------------------------------------------------------------
// SpMM: g_support[N,128] = adj(fp32, cvt to bf16 by producers) @ g_featb[N,128]
// Warp-specialized: warps 0-3 consume (ldmatrix+mma), warps 4-7 produce.
// CTA tile 64(M) x 128(N), BK=64, 4-stage mbarrier ring, occ 2.
//  A: LDG.128 fp32 (2-deep register staging) -> cvt bf16 -> swizzled STS.
//  B: cp.async bf16 (L2-hot).
// Consumer warp grid 2(M) x 2(N): 32x64 per warp, mma.sync.m16n8k16 bf16/f32.
// ---------------------------------------------------------------------------
__global__ void __launch_bounds__(256, 2)
spmm_kernel(const float* __restrict__ A) {
    extern __shared__ char smem[];
    // per stage: A 64x64 bf16 (128B/row) = 8192 ; B 64x128 bf16 (256B/row) = 16384
    char* As = smem;                         // STAGES * 8192
    char* Bs = smem + STAGES * 8192;         // STAGES * 16384
    __shared__ uint64_t bar_full[STAGES];
    __shared__ uint64_t bar_empty[STAGES];
    const uint32_t as0 = smaddr(As);
    const uint32_t bs0 = smaddr(Bs);
    const uint32_t bf0 = smaddr(&bar_full[0]);
    const uint32_t be0 = smaddr(&bar_empty[0]);

    const int t    = threadIdx.x;
    const int lane = t & 31;
    const int warp = t >> 5;
    const int m0 = blockIdx.x * BM;

    if (t == 0) {
        #pragma unroll
        for (int s = 0; s < STAGES; ++s) {
            mbar_init(bf0 + s * 8, 128);   // producers arrive
            mbar_init(be0 + s * 8, 128);   // consumers arrive
        }
    }
    __syncthreads();

    if (warp >= 4) {
        // ===================== PRODUCER (warps 4-7) =====================
        const int pt = t - 128;            // 0..127
        const int ar = pt >> 4;            // 0..7
        const int af = pt & 15;            // float4 slot within 64-float row
        const float* Abase = A + (size_t)m0 * N_NODES;

        float4 regA[8], regB[8];

        auto ldgA = [&](int kt, float4 (&rg)[8]) {
            const float* src = Abase + (size_t)kt * BK + af * 4;
            #pragma unroll
            for (int p = 0; p < 8; ++p) {
                int r = p * 8 + ar;
                rg[p] = *(const float4*)(src + (size_t)r * N_NODES);
            }
        };
        auto stsA = [&](int slot, const float4 (&rg)[8]) {
            char* dst = As + slot * 8192;
            const int c = af >> 1, h = af & 1;
            #pragma unroll
            for (int p = 0; p < 8; ++p) {
                int r = p * 8 + ar;
                int off = r * 128 + (((c ^ (r & 7)) << 4) | (h << 3));
                __nv_bfloat162 lo = __float22bfloat162_rn(make_float2(rg[p].x, rg[p].y));
                __nv_bfloat162 hi = __float22bfloat162_rn(make_float2(rg[p].z, rg[p].w));
                uint2 v;
                v.x = *(uint32_t*)&lo;
                v.y = *(uint32_t*)&hi;
                *(uint2*)(dst + off) = v;
            }
        };
        auto cpB = [&](int kt, int slot) {
            const char* gsrc = (const char*)(g_featb + (size_t)kt * BK * FDIM);
            const uint32_t sbase = bs0 + slot * 16384;
            #pragma unroll
            for (int p = 0; p < 8; ++p) {
                int idx = pt + p * 128;     // 0..1023
                int r = idx >> 4;           // 0..63
                int c = idx & 15;
                uint32_t soff = r * 256 + ((c ^ ((r & 7) << 1)) << 4);
                asm volatile("cp.async.cg.shared.global [%0], [%1], 16;\n"
                             :: "r"(sbase + soff), "l"(gsrc + (size_t)r * 256 + c * 16));
            }
        };

        // prologue: tile 0 into flight
        mbar_wait(be0 + 0, 1);             // empty[0], parity 1 -> immediate
        cpB(0, 0);
        asm volatile("cp.async.commit_group;\n");
        ldgA(0, regA);

        #pragma unroll 1
        for (int tt = 0; tt < KTILES; tt += 2) {
            // ---- even tile tt (data in regA), prefetch tt+1 into regB
            {
                const int nt = tt + 1;
                const int ns = nt & (STAGES - 1);
                mbar_wait(be0 + ns * 8, ((nt >> 2) & 1) ^ 1);
                cpB(nt, ns);
                asm volatile("cp.async.commit_group;\n");
                ldgA(nt, regB);
                stsA(tt & (STAGES - 1), regA);
                asm volatile("cp.async.wait_group 1;\n");
                mbar_arrive(bf0 + (tt & (STAGES - 1)) * 8);
            }
            // ---- odd tile tt+1 (data in regB), prefetch tt+2 into regA
            {
                const int ct = tt + 1;
                const int nt = tt + 2;
                if (nt < KTILES) {
                    const int ns = nt & (STAGES - 1);
                    mbar_wait(be0 + ns * 8, ((nt >> 2) & 1) ^ 1);
                    cpB(nt, ns);
                    asm volatile("cp.async.commit_group;\n");
                    ldgA(nt, regA);
                    stsA(ct & (STAGES - 1), regB);
                    asm volatile("cp.async.wait_group 1;\n");
                } else {
                    stsA(ct & (STAGES - 1), regB);
                    asm volatile("cp.async.wait_group 0;\n");
                }
                mbar_arrive(bf0 + (ct & (STAGES - 1)) * 8);
            }
        }
    } else {
        // ===================== CONSUMER (warps 0-3) =====================
        const int wm = warp & 1;       // 0..1 (M groups of 32)
        const int wn = warp >> 1;      // 0..1 (N groups of 64)

        float acc[2][8][4];
        #pragma unroll
        for (int i = 0; i < 2; ++i)
            #pragma unroll
            for (int j = 0; j < 8; ++j)
                #pragma unroll
                for (int k = 0; k < 4; ++k) acc[i][j][k] = 0.f;

        #pragma unroll 1
        for (int tt = 0; tt < KTILES; ++tt) {
            const int slot = tt & (STAGES - 1);
            mbar_wait(bf0 + slot * 8, (tt >> 2) & 1);
            const uint32_t ab = as0 + slot * 8192;
            const uint32_t bb = bs0 + slot * 16384;
            #pragma unroll
            for (int ks = 0; ks < 4; ++ks) {
                uint32_t a[2][4];
                #pragma unroll
                for (int mt = 0; mt < 2; ++mt) {
                    int r = wm * 32 + mt * 16 + (lane & 15);
                    int c = ks * 2 + (lane >> 4);
                    uint32_t addr = ab + r * 128 + ((c ^ (r & 7)) << 4);
                    asm volatile("ldmatrix.sync.aligned.m8n8.x4.shared.b16 {%0,%1,%2,%3}, [%4];\n"
                        : "=r"(a[mt][0]), "=r"(a[mt][1]), "=r"(a[mt][2]), "=r"(a[mt][3])
                        : "r"(addr));
                }
                uint32_t b[8][2];
                #pragma unroll
                for (int nt = 0; nt < 8; ++nt) {
                    int r = ks * 16 + (lane & 15);
                    int c = wn * 8 + nt;
                    uint32_t addr = bb + r * 256 + ((c ^ ((r & 7) << 1)) << 4);
                    asm volatile("ldmatrix.sync.aligned.m8n8.x2.trans.shared.b16 {%0,%1}, [%2];\n"
                        : "=r"(b[nt][0]), "=r"(b[nt][1]) : "r"(addr));
                }
                #pragma unroll
                for (int mt = 0; mt < 2; ++mt)
                    #pragma unroll
                    for (int nt = 0; nt < 8; ++nt) {
                        asm volatile(
                            "mma.sync.aligned.m16n8k16.row.col.f32.bf16.bf16.f32 "
                            "{%0,%1,%2,%3}, {%4,%5,%6,%7}, {%8,%9}, {%0,%1,%2,%3};\n"
                            : "+f"(acc[mt][nt][0]), "+f"(acc[mt][nt][1]),
                              "+f"(acc[mt][nt][2]), "+f"(acc[mt][nt][3])
                            : "r"(a[mt][0]), "r"(a[mt][1]), "r"(a[mt][2]), "r"(a[mt][3]),
                              "r"(b[nt][0]), "r"(b[nt][1]));
                    }
            }
            mbar_arrive(be0 + slot * 8);
        }

        // Epilogue: fragment -> g_support (fp32, row-major)
        float* Cp = g_support + (size_t)m0 * FDIM;
        #pragma unroll
        for (int mt = 0; mt < 2; ++mt) {
            int r0 = wm * 32 + mt * 16 + (lane >> 2);
            #pragma unroll
            for (int nt = 0; nt < 8; ++nt) {
                int c0 = wn * 64 + nt * 8 + (lane & 3) * 2;
                *(float2*)(Cp + (size_t)r0 * FDIM + c0)       = make_float2(acc[mt][nt][0], acc[mt][nt][1]);
                *(float2*)(Cp + (size_t)(r0 + 8) * FDIM + c0) = make_float2(acc[mt][nt][2], acc[mt][nt][3]);
            }
        }
    }
}

// ---------------------------------------------------------------------------
// h = relu( [X | g_support] @ W + b ), W is [256,128].
// Writes fp32 to `out`; optionally also bf16 to g_featb (input to next SpMM).
// ---------------------------------------------------------------------------
__global__ void __launch_bounds__(256)
sage_linear_kernel(const float* __restrict__ X,
                   const float* __restrict__ W,
                   const float* __restrict__ bias,
                   float* __restrict__ out,
                   int write_bf16) {
    __shared__ float INs[64][16];
    __shared__ float Ws[16][128];
    const int t  = threadIdx.x;
    const int tr = t >> 5;
    const int tc = t & 31;
    const int row0 = blockIdx.x * 64;

    float acc[8][4];
    #pragma unroll
    for (int i = 0; i < 8; ++i)
        #pragma unroll
        for (int j = 0; j < 4; ++j) acc[i][j] = 0.f;

    for (int kb = 0; kb < 16; ++kb) {
        const int kbase = kb * 16;
        #pragma unroll
        for (int j = 0; j < 4; ++j) {
            int idx = t + j * 256;
            int r = idx >> 4, kk = idx & 15;
            int k = kbase + kk;
            float v;
            if (k < FDIM) v = X[(size_t)(row0 + r) * FDIM + k];
            else          v = g_support[(size_t)(row0 + r) * FDIM + (k - FDIM)];
            INs[r][kk] = v;
        }
        #pragma unroll
        for (int j = 0; j < 8; ++j) {
            int idx = t + j * 256;
            int wr = idx >> 7, wc = idx & 127;
            Ws[wr][wc] = W[(size_t)(kbase + wr) * FDIM + wc];
        }
        __syncthreads();
        #pragma unroll
        for (int kk = 0; kk < 16; ++kk) {
            float4 w = *(const float4*)&Ws[kk][tc * 4];
            #pragma unroll
            for (int i = 0; i < 8; ++i) {
                float xv = INs[tr * 8 + i][kk];
                acc[i][0] = fmaf(xv, w.x, acc[i][0]);
                acc[i][1] = fmaf(xv, w.y, acc[i][1]);
                acc[i][2] = fmaf(xv, w.z, acc[i][2]);
                acc[i][3] = fmaf(xv, w.w, acc[i][3]);
            }
        }
        __syncthreads();
    }

    const float4 bv = *(const float4*)&bias[tc * 4];
    #pragma unroll
    for (int i = 0; i < 8; ++i) {
        int r = row0 + tr * 8 + i;
        float4 o;
        o.x = fmaxf(acc[i][0] + bv.x, 0.f);
        o.y = fmaxf(acc[i][1] + bv.y, 0.f);
        o.z = fmaxf(acc[i][2] + bv.z, 0.f);
        o.w = fmaxf(acc[i][3] + bv.w, 0.f);
        *(float4*)&out[(size_t)r * FDIM + tc * 4] = o;
        if (write_bf16) {
            __nv_bfloat162 lo = __float22bfloat162_rn(make_float2(o.x, o.y));
            __nv_bfloat162 hi = __float22bfloat162_rn(make_float2(o.z, o.w));
            uint2 v;
            v.x = *(uint32_t*)&lo;
            v.y = *(uint32_t*)&hi;
            *(uint2*)&g_featb[(size_t)r * FDIM + tc * 4] = v;
        }
    }
}

// ---------------------------------------------------------------------------
// logits = h2 @ Wl + bl ; log_probs = logits - logsumexp(logits)
// ---------------------------------------------------------------------------
__global__ void __launch_bounds__(128)
classifier_kernel(const float* __restrict__ H,
                  const float* __restrict__ Wl,
                  const float* __restrict__ bl,
                  float* __restrict__ logp,
                  float* __restrict__ logits) {
    extern __shared__ float sh[];
    float* Hs  = sh;                  // 128*129
    float* Wls = sh + 128 * 129;      // 128*40
    float* bls = Wls + 128 * NCLS;    // 40
    const int t = threadIdx.x;
    const int row0 = blockIdx.x * 128;

    for (int j = 0; j < 128; ++j)
        Hs[j * 129 + t] = H[(size_t)(row0 + j) * FDIM + t];
    for (int idx = t; idx < 128 * NCLS; idx += 128)
        Wls[idx] = Wl[idx];
    if (t < NCLS) bls[t] = bl[t];
    __syncthreads();

    float acc[NCLS];
    #pragma unroll
    for (int c = 0; c < NCLS; ++c) acc[c] = bls[c];

    const float* hr = &Hs[t * 129];
    #pragma unroll 4
    for (int k = 0; k < FDIM; ++k) {
        float xv = hr[k];
        #pragma unroll
        for (int c = 0; c < NCLS; c += 4) {
            float4 w = *(const float4*)&Wls[k * NCLS + c];
            acc[c + 0] = fmaf(xv, w.x, acc[c + 0]);
            acc[c + 1] = fmaf(xv, w.y, acc[c + 1]);
            acc[c + 2] = fmaf(xv, w.z, acc[c + 2]);
            acc[c + 3] = fmaf(xv, w.w, acc[c + 3]);
        }
    }

    float m = acc[0];
    #pragma unroll
    for (int c = 1; c < NCLS; ++c) m = fmaxf(m, acc[c]);
    float s = 0.f;
    #pragma unroll
    for (int c = 0; c < NCLS; ++c) s += __expf(acc[c] - m);
    float lse = m + __logf(s);

    size_t ro = (size_t)(row0 + t) * NCLS;
    #pragma unroll
    for (int c = 0; c < NCLS; ++c) {
        logits[ro + c] = acc[c];
        logp[ro + c]   = acc[c] - lse;
    }
}

// ---------------------------------------------------------------------------
extern "C" void kernel_launch(void* const* d_in, const int* in_sizes, int n_in,
                              void* d_out, int out_size) {
    (void)in_sizes; (void)n_in; (void)out_size;
    const float* x   = (const float*)d_in[0];
    const float* adj = (const float*)d_in[1];
    const float* W1  = (const float*)d_in[2];
    const float* b1  = (const float*)d_in[3];
    const float* W2  = (const float*)d_in[4];
    const float* b2  = (const float*)d_in[5];
    const float* Wl  = (const float*)d_in[6];
    const float* bl  = (const float*)d_in[7];

    float* out    = (float*)d_out;
    float* logp   = out;                                  // [N, 40]
    float* h1     = logp + (size_t)N_NODES * NCLS;        // [N, 128]
    float* h2     = h1 + (size_t)N_NODES * FDIM;          // [N, 128]
    float* logits = h2 + (size_t)N_NODES * FDIM;          // [N, 40]

    const int cls_smem  = (128 * 129 + 128 * NCLS + NCLS) * (int)sizeof(float);
    const int spmm_smem = STAGES * (8192 + 16384);   // 96 KB
    cudaFuncSetAttribute(spmm_kernel, cudaFuncAttributeMaxDynamicSharedMemorySize, spmm_smem);
    cudaFuncSetAttribute(classifier_kernel, cudaFuncAttributeMaxDynamicSharedMemorySize, cls_smem);

    // 1) x -> bf16
    cvt_x_kernel<<<512, 256>>>(x);
    // 2) support = adj @ x
    spmm_kernel<<<N_NODES / BM, 256, spmm_smem>>>(adj);
    // 3) h1 = relu([x|s]@W1 + b1)  (also emits bf16 h1 into g_featb)
    sage_linear_kernel<<<N_NODES / 64, 256>>>(x, W1, b1, h1, 1);
    // 4) support = adj @ h1
    spmm_kernel<<<N_NODES / BM, 256, spmm_smem>>>(adj);
    // 5) h2 = relu([h1|s]@W2 + b2)
    sage_linear_kernel<<<N_NODES / 64, 256>>>(h1, W2, b2, h2, 0);
    // 6) logits + log_softmax
    classifier_kernel<<<N_NODES / 128, 128, cls_smem>>>(h2, Wl, bl, logp, logits);
}